// round 1
// baseline (speedup 1.0000x reference)
#include <cuda_runtime.h>

#define HH 512
#define WW 512
#define HWSZ (HH * WW)

// accumulators: 0=focal_sum, 1=sum(p*t), 2=sum(p), 3=sum(t), 4=sum(bce*w)
__device__ double g_acc[5];

__global__ void init_acc_kernel() {
    if (threadIdx.x < 5) g_acc[threadIdx.x] = 0.0;
}

__global__ void __launch_bounds__(256) combined_loss_kernel(
    const float* __restrict__ inp,
    const float* __restrict__ tgt,
    int ngroups)  // total_pixels / 4
{
    float a_focal = 0.f, a_spt = 0.f, a_sp = 0.f, a_st = 0.f, a_sbw = 0.f;

    const int stride = gridDim.x * blockDim.x;
    for (int g = blockIdx.x * blockDim.x + threadIdx.x; g < ngroups; g += stride) {
        const int pix = g << 2;               // first pixel of group (4 consecutive, same row)
        const int img = pix / HWSZ;
        const int rem = pix - img * HWSZ;
        const int y   = rem >> 9;             // W = 512
        const int x0  = rem & (WW - 1);

        const float* tb = tgt + (size_t)img * HWSZ;

        // Row bitmasks; bit k <-> column x0-2+k  (k = 0..7)
        unsigned m0 = 0, mu1 = 0, md1 = 0, mu2 = 0, md2 = 0;

        // center float4 loads (cols x0..x0+3 -> bits 2..5)
        {
            float4 v = *reinterpret_cast<const float4*>(tb + y * WW + x0);
            m0 |= (v.x > 0.5f ? 4u : 0u) | (v.y > 0.5f ? 8u : 0u) |
                  (v.z > 0.5f ? 16u : 0u) | (v.w > 0.5f ? 32u : 0u);
        }
        if (y >= 1) {
            float4 v = *reinterpret_cast<const float4*>(tb + (y - 1) * WW + x0);
            mu1 |= (v.x > 0.5f ? 4u : 0u) | (v.y > 0.5f ? 8u : 0u) |
                   (v.z > 0.5f ? 16u : 0u) | (v.w > 0.5f ? 32u : 0u);
        }
        if (y < HH - 1) {
            float4 v = *reinterpret_cast<const float4*>(tb + (y + 1) * WW + x0);
            md1 |= (v.x > 0.5f ? 4u : 0u) | (v.y > 0.5f ? 8u : 0u) |
                   (v.z > 0.5f ? 16u : 0u) | (v.w > 0.5f ? 32u : 0u);
        }
        if (y >= 2) {
            float4 v = *reinterpret_cast<const float4*>(tb + (y - 2) * WW + x0);
            mu2 |= (v.x > 0.5f ? 4u : 0u) | (v.y > 0.5f ? 8u : 0u) |
                   (v.z > 0.5f ? 16u : 0u) | (v.w > 0.5f ? 32u : 0u);
        }
        if (y < HH - 2) {
            float4 v = *reinterpret_cast<const float4*>(tb + (y + 2) * WW + x0);
            md2 |= (v.x > 0.5f ? 4u : 0u) | (v.y > 0.5f ? 8u : 0u) |
                   (v.z > 0.5f ? 16u : 0u) | (v.w > 0.5f ? 32u : 0u);
        }

        // left edge (cols x0-2, x0-1)
        if (x0 > 0) {
            float2 vl = *reinterpret_cast<const float2*>(tb + y * WW + x0 - 2);
            m0 |= (vl.x > 0.5f ? 1u : 0u) | (vl.y > 0.5f ? 2u : 0u);
            if (y >= 1)      mu1 |= (tb[(y - 1) * WW + x0 - 1] > 0.5f ? 2u : 0u);
            if (y < HH - 1)  md1 |= (tb[(y + 1) * WW + x0 - 1] > 0.5f ? 2u : 0u);
        }
        // right edge (cols x0+4, x0+5)
        if (x0 + 4 < WW) {
            float2 vr = *reinterpret_cast<const float2*>(tb + y * WW + x0 + 4);
            m0 |= (vr.x > 0.5f ? 64u : 0u) | (vr.y > 0.5f ? 128u : 0u);
            if (y >= 1)      mu1 |= (tb[(y - 1) * WW + x0 + 4] > 0.5f ? 64u : 0u);
            if (y < HH - 1)  md1 |= (tb[(y + 1) * WW + x0 + 4] > 0.5f ? 64u : 0u);
        }

        const float4 xi = *reinterpret_cast<const float4*>(inp + (size_t)img * HWSZ + y * WW + x0);
        float xv[4] = { xi.x, xi.y, xi.z, xi.w };

        #pragma unroll
        for (int j = 0; j < 4; j++) {
            const float x = xv[j];
            const unsigned tbit = (m0 >> (j + 2)) & 1u;
            const float t = (float)tbit;

            const float e = __expf(-fabsf(x));
            const float l = log1pf(e);
            const float bce = fmaxf(x, 0.f) - x * t + l;

            const float r = __fdividef(1.f, 1.f + e);
            const float p = (x >= 0.f) ? r : e * r;

            // pt = exp(-bce) == (t ? p : 1-p) exactly for t in {0,1}
            const float ompt = tbit ? (1.f - p) : p;   // 1 - pt
            a_focal += (0.25f * ompt * ompt) * bce;
            a_sp  += p;
            a_st  += t;
            a_spt += tbit ? p : 0.f;

            // diamond radius-2 any/all (OOB rows/cols contribute 0 bits)
            const unsigned c0 = (m0  >> j)       & 0x1Fu;
            const unsigned cu = (mu1 >> (j + 1)) & 0x7u;
            const unsigned cd = (md1 >> (j + 1)) & 0x7u;
            const unsigned eu = (mu2 >> (j + 2)) & 1u;
            const unsigned ed = (md2 >> (j + 2)) & 1u;
            const bool any = (c0 | cu | cd | eu | ed) != 0u;
            const bool all = (c0 == 0x1Fu) & (cu == 0x7u) & (cd == 0x7u) & (eu != 0u) & (ed != 0u);
            const float w = (any && !all) ? 6.f : 1.f;
            a_sbw += bce * w;
        }
    }

    // warp reduce 5 values
    float v[5] = { a_focal, a_spt, a_sp, a_st, a_sbw };
    #pragma unroll
    for (int q = 0; q < 5; q++) {
        #pragma unroll
        for (int off = 16; off > 0; off >>= 1)
            v[q] += __shfl_down_sync(0xFFFFFFFFu, v[q], off);
    }

    __shared__ float s[8][5];
    const int wid = threadIdx.x >> 5;
    const int lid = threadIdx.x & 31;
    if (lid == 0) {
        #pragma unroll
        for (int q = 0; q < 5; q++) s[wid][q] = v[q];
    }
    __syncthreads();
    if (threadIdx.x == 0) {
        #pragma unroll
        for (int q = 0; q < 5; q++) {
            float acc = 0.f;
            #pragma unroll
            for (int w = 0; w < 8; w++) acc += s[w][q];
            atomicAdd(&g_acc[q], (double)acc);
        }
    }
}

__global__ void finalize_kernel(float* out, double invN) {
    const double focal = g_acc[0] * invN;
    const double spt = g_acc[1], sp = g_acc[2], st = g_acc[3];
    const double dice = (2.0 * spt + 1e-6) / (sp + st + 1e-6);
    const double bl = g_acc[4] * invN;
    out[0] = (float)(0.3 * focal + 0.4 * (1.0 - dice) + 0.3 * bl);
}

extern "C" void kernel_launch(void* const* d_in, const int* in_sizes, int n_in,
                              void* d_out, int out_size) {
    const float* inp = (const float*)d_in[0];
    const float* tgt = (const float*)d_in[1];
    const int N = in_sizes[0];
    const int ngroups = N >> 2;

    init_acc_kernel<<<1, 32>>>();
    combined_loss_kernel<<<1184, 256>>>(inp, tgt, ngroups);
    finalize_kernel<<<1, 1>>>((float*)d_out, 1.0 / (double)N);
}